// round 15
// baseline (speedup 1.0000x reference)
#include <cuda_runtime.h>
#include <cstdint>

// DWTModelFullBand: the reference computes idwt2(idwt2(dwt2(dwt2(x)))) with
// exact algebraic inverses (a=(ll-lh-hl+hh)/2 = 4a/4 symbolically); all
// stacks/reshapes are layout-only. Hence output == input up to fp32 rounding
// (measured rel_err 6.2e-8 << 1e-3). The required work is exactly a 96 MiB
// device-to-device copy — an irreducible 96MB read + 96MB write.
//
// FINAL: single copy-engine memcpy graph node. Fully mapped design space:
//   R2  SM float4 copy:          31.1us device, dur 39.4
//   R4  SM f8 + evict hints:     27.2us device, dur 36.8
//   R5  L2 evict_last pinning:   refuted (hints inert without carveout)
//   R6  burst-batched/tail-free: neutral (DRAM-bound; issue=2.1%)
//   R8+ single CE memcpy node:   ~25.7us device (~94% of 8TB/s HBM spec),
//                                dur 35.3/35.5/37.4/35.3 across reruns <= BEST
//   R9  dual-CE fork/join:       38.1 (event nodes +2.8us; DRAM-bound, not
//                                CE-bound -> no device gain)
// No PTX G2G bulk-copy path exists; SMEM staging adds a hop. Harness noise
// +-1-2us; dur-device gap (~9.6us) is fixed graph-replay overhead,
// engine-independent. Converged at the memory roofline for an identity copy.

extern "C" void kernel_launch(void* const* d_in, const int* in_sizes, int n_in,
                              void* d_out, int out_size) {
    size_t bytes = (size_t)in_sizes[0] * sizeof(float);  // 96 MiB
    cudaMemcpyAsync(d_out, d_in[0], bytes, cudaMemcpyDeviceToDevice, 0);
}